// round 7
// baseline (speedup 1.0000x reference)
#include <cuda_runtime.h>
#include <math.h>

// Problem constants
#define BB 2
#define TT 2048
#define EE 1024
#define HH 16
#define DD 64
#define WW 64

// GEMM tiling
#define BM 128
#define BN 128
#define BK 32
#define NIT (EE / BK)

// Attention tiling
#define KCH 48
#define KST 68
#define VST 72
#define PST 52
#define KS_OFF 0
#define VS_OFF (KCH * KST)
#define PQ_OFF (VS_OFF + KCH * VST)
#define SM_TOT (PQ_OFF + 4 * 16 * PST)

// Scratch: attention output (tf32-rounded bits stored as float) and tf32 W
__device__ float g_y[BB * TT * EE];
__device__ unsigned g_w32[EE * EE];

__device__ __forceinline__ unsigned f2tf32(float f) {
    unsigned u;
    asm("cvt.rna.tf32.f32 %0, %1;" : "=r"(u) : "f"(f));
    return u;
}

__device__ __forceinline__ void mma_tf32(float c[4], const unsigned a[4],
                                         unsigned b0, unsigned b1) {
    asm volatile(
        "mma.sync.aligned.m16n8k8.row.col.f32.tf32.tf32.f32 "
        "{%0,%1,%2,%3}, {%4,%5,%6,%7}, {%8,%9}, {%0,%1,%2,%3};\n"
        : "+f"(c[0]), "+f"(c[1]), "+f"(c[2]), "+f"(c[3])
        : "r"(a[0]), "r"(a[1]), "r"(a[2]), "r"(a[3]), "r"(b0), "r"(b1));
}

// ---------------------------------------------------------------------------
// MMA windowed attention + W tf32 pre-conversion slice.
// Grid (T/64, H, B) = 1024 blocks, 128 threads.
// ---------------------------------------------------------------------------
__global__ void __launch_bounds__(128, 4)
attn_mma_kernel(const float* __restrict__ q, const float* __restrict__ k,
                const float* __restrict__ v, const float* __restrict__ W) {
    __shared__ unsigned sm[SM_TOT];

    const int tid = threadIdx.x;
    const int lane = tid & 31;
    const int w = tid >> 5;
    const int g = lane >> 2;
    const int tg = lane & 3;
    const int qb = blockIdx.x * 64;
    const int h = blockIdx.y;
    const int b = blockIdx.z;
    const int kb = qb - WW;

    // ---- W -> tf32 conversion slice (1024 blocks x 1024 floats covers W)
    {
        const int blin = (blockIdx.z * HH + blockIdx.y) * (TT / 64) + blockIdx.x;
        const float4* src = (const float4*)&W[(size_t)blin * 1024] + tid;
        uint4* dst = (uint4*)&g_w32[(size_t)blin * 1024] + tid;
#pragma unroll
        for (int i = 0; i < 2; i++) {
            float4 x = src[i * 128];
            dst[i * 128] = make_uint4(f2tf32(x.x), f2tf32(x.y), f2tf32(x.z), f2tf32(x.w));
        }
    }

    // ---- stage Q (pre-scaled by 1/8, tf32)
    {
        const int row = tid >> 1;
        const int s0 = (tid & 1) * 8;
        const float* src = q + ((size_t)(b * TT + qb + row) * EE + h * DD) + s0 * 4;
        unsigned* dst = &sm[row * KST + s0 * 4];
#pragma unroll
        for (int i = 0; i < 8; i++) {
            float4 x = ((const float4*)src)[i];
            ((uint4*)dst)[i] = make_uint4(f2tf32(x.x * 0.125f), f2tf32(x.y * 0.125f),
                                          f2tf32(x.z * 0.125f), f2tf32(x.w * 0.125f));
        }
    }
    __syncthreads();

    unsigned aQ[8][4];
#pragma unroll
    for (int kc = 0; kc < 8; kc++) {
        const unsigned* p0 = &sm[(w * 16 + g) * KST + kc * 8 + tg];
        aQ[kc][0] = p0[0];
        aQ[kc][1] = p0[8 * KST];
        aQ[kc][2] = p0[4];
        aQ[kc][3] = p0[8 * KST + 4];
    }
    __syncthreads();

    float oacc[8][4];
#pragma unroll
    for (int i = 0; i < 8; i++)
#pragma unroll
        for (int r = 0; r < 4; r++) oacc[i][r] = 0.f;
    float l0 = 0.f, l1 = 0.f;

    const int qr0 = qb + w * 16 + g;
    const int qr1 = qr0 + 8;
    const unsigned pw = PQ_OFF + w * 16 * PST;

    for (int cc = 0; cc < 4; ++cc) {
        if (cc) __syncthreads();
        {
            const int r0 = tid >> 4;
            const int sg = tid & 15;
#pragma unroll
            for (int i = 0; i < 6; i++) {
                const int row = r0 + i * 8;
                const int j = kb + cc * KCH + row;
                float4 kx = make_float4(0.f, 0.f, 0.f, 0.f);
                float4 vx = kx;
                if (j >= 0 && j < TT) {
                    const size_t base = (size_t)(b * TT + j) * EE + h * DD + sg * 4;
                    kx = *(const float4*)(k + base);
                    vx = *(const float4*)(v + base);
                }
                *(uint4*)&sm[KS_OFF + row * KST + sg * 4] =
                    make_uint4(f2tf32(kx.x), f2tf32(kx.y), f2tf32(kx.z), f2tf32(kx.w));
                *(uint4*)&sm[VS_OFF + row * VST + sg * 4] =
                    make_uint4(f2tf32(vx.x), f2tf32(vx.y), f2tf32(vx.z), f2tf32(vx.w));
            }
        }
        __syncthreads();

        float sacc[6][4];
#pragma unroll
        for (int i = 0; i < 6; i++)
#pragma unroll
            for (int r = 0; r < 4; r++) sacc[i][r] = 0.f;
#pragma unroll
        for (int n8 = 0; n8 < 6; n8++) {
            const unsigned* kr = &sm[KS_OFF + (n8 * 8 + g) * KST + tg];
#pragma unroll
            for (int kc = 0; kc < 8; kc++)
                mma_tf32(sacc[n8], aQ[kc], kr[kc * 8], kr[kc * 8 + 4]);
        }

#pragma unroll
        for (int n8 = 0; n8 < 6; n8++) {
            const int j0 = kb + cc * KCH + n8 * 8 + 2 * tg;
            const int j1 = j0 + 1;
            const bool v00 = (j0 >= 0) & (j0 < TT) & (abs(qr0 - j0) <= WW);
            const bool v01 = (j1 >= 0) & (j1 < TT) & (abs(qr0 - j1) <= WW);
            const bool v10 = (j0 >= 0) & (j0 < TT) & (abs(qr1 - j0) <= WW);
            const bool v11 = (j1 >= 0) & (j1 < TT) & (abs(qr1 - j1) <= WW);
            const float p0 = v00 ? __expf(sacc[n8][0]) : 0.f;
            const float p1 = v01 ? __expf(sacc[n8][1]) : 0.f;
            const float p2 = v10 ? __expf(sacc[n8][2]) : 0.f;
            const float p3 = v11 ? __expf(sacc[n8][3]) : 0.f;
            l0 += p0 + p1;
            l1 += p2 + p3;
            *(uint2*)&sm[pw + g * PST + n8 * 8 + 2 * tg] =
                make_uint2(f2tf32(p0), f2tf32(p1));
            *(uint2*)&sm[pw + (g + 8) * PST + n8 * 8 + 2 * tg] =
                make_uint2(f2tf32(p2), f2tf32(p3));
        }
        __syncwarp();

#pragma unroll
        for (int kk = 0; kk < 6; kk++) {
            unsigned aP[4];
            const unsigned* pp = &sm[pw + g * PST + kk * 8 + tg];
            aP[0] = pp[0];
            aP[1] = pp[8 * PST];
            aP[2] = pp[4];
            aP[3] = pp[8 * PST + 4];
            const unsigned* vr = &sm[VS_OFF + (kk * 8 + tg) * VST + g];
            const unsigned* vr4 = vr + 4 * VST;
#pragma unroll
            for (int n8 = 0; n8 < 8; n8++)
                mma_tf32(oacc[n8], aP, vr[n8 * 8], vr4[n8 * 8]);
        }
        __syncwarp();
    }

    l0 += __shfl_xor_sync(0xffffffffu, l0, 1);
    l0 += __shfl_xor_sync(0xffffffffu, l0, 2);
    l1 += __shfl_xor_sync(0xffffffffu, l1, 1);
    l1 += __shfl_xor_sync(0xffffffffu, l1, 2);
    const float i0 = 1.f / l0, i1 = 1.f / l1;

    // store tf32-rounded y so proj can consume raw bits
#pragma unroll
    for (int n8 = 0; n8 < 8; n8++) {
        const int col = h * DD + n8 * 8 + 2 * tg;
        *(uint2*)&g_y[(size_t)(b * TT + qr0) * EE + col] =
            make_uint2(f2tf32(oacc[n8][0] * i0), f2tf32(oacc[n8][1] * i0));
        *(uint2*)&g_y[(size_t)(b * TT + qr1) * EE + col] =
            make_uint2(f2tf32(oacc[n8][2] * i1), f2tf32(oacc[n8][3] * i1));
    }
}

// ---------------------------------------------------------------------------
// tf32 tensor-core projection: 256 threads (8 warps, 2x4 layout of 64x32
// warp tiles), double-buffered fragment-major smem, register prefetch.
// ---------------------------------------------------------------------------
__device__ __forceinline__ void proj_store(unsigned* Ad, unsigned* Bd,
                                           const uint4* pa, const uint4* pb,
                                           int ihalf, int ks_w, int ch_w,
                                           int hi_w, int gp_w) {
    const int slotA = hi_w + 2 * ch_w;
#pragma unroll
    for (int ii = 0; ii < 4; ii++) {
        const int i = ihalf * 4 + ii;
        *(uint4*)&Ad[(ks_w * 8 + i) * 128 + slotA * 32 + gp_w] = pa[ii];
        *(uint4*)&Bd[(ks_w * 16 + i * 2 + hi_w) * 64 + ch_w * 32 + gp_w] = pb[ii];
    }
}

__global__ void __launch_bounds__(256, 3) proj_kernel(const float* __restrict__ bias,
                                                      float* __restrict__ out) {
    __shared__ unsigned As[2][4 * 8 * 128];
    __shared__ unsigned Bs[2][4 * 16 * 64];

    const int tid = threadIdx.x;
    const int m0 = blockIdx.y * BM;
    const int n0 = blockIdx.x * BN;

    // loader mapping: base role (as in 128-thr version) + i-half split
    const int base = tid & 127;
    const int ihalf = tid >> 7;
    const int seg = base & 7;
    const int rb = base >> 3;
    const int hi_w = rb >> 3;
    const int ks_w = seg >> 1;
    const int ch_w = seg & 1;
    const int gp_w = ((rb & 7) ^ (ks_w ^ (ch_w << 2))) << 2;

    const unsigned* ysrc = (const unsigned*)g_y;
    const unsigned* asrc = &ysrc[(size_t)(m0 + ihalf * 64 + rb) * EE + seg * 4];
    const unsigned* bsrc = &g_w32[(size_t)(n0 + ihalf * 64 + rb) * EE + seg * 4];

    // compute mapping: 8 warps, 2 (m) x 4 (n)
    const int lane = tid & 31;
    const int wid = tid >> 5;
    const int mw = wid >> 2;       // 0..1 -> 64 rows
    const int nw = wid & 3;        // 0..3 -> 32 cols
    const int g = lane >> 2;
    const int tg = lane & 3;

    float acc[4][4][4];
#pragma unroll
    for (int i = 0; i < 4; i++)
#pragma unroll
        for (int j = 0; j < 4; j++)
#pragma unroll
            for (int r = 0; r < 4; r++) acc[i][j][r] = 0.f;

    uint4 pa[4], pb[4];
#pragma unroll
    for (int ii = 0; ii < 4; ii++) {
        pa[ii] = *(const uint4*)&asrc[(size_t)ii * 16 * EE];
        pb[ii] = *(const uint4*)&bsrc[(size_t)ii * 16 * EE];
    }
    proj_store(As[0], Bs[0], pa, pb, ihalf, ks_w, ch_w, hi_w, gp_w);
    __syncthreads();

    for (int it = 0; it < NIT; ++it) {
        const unsigned* Ac = As[it & 1];
        const unsigned* Bc = Bs[it & 1];

        if (it + 1 < NIT) {
            const int kk = (it + 1) * BK;
#pragma unroll
            for (int ii = 0; ii < 4; ii++) {
                pa[ii] = *(const uint4*)&asrc[(size_t)ii * 16 * EE + kk];
                pb[ii] = *(const uint4*)&bsrc[(size_t)ii * 16 * EE + kk];
            }
        }

#pragma unroll
        for (int ks = 0; ks < 4; ++ks) {
            const int ilo = ((g ^ ks) << 2) + tg;
            const int ihi = ((g ^ ks ^ 4) << 2) + tg;
            unsigned af[4][4];
#pragma unroll
            for (int mt = 0; mt < 4; mt++) {
                const unsigned* ab = &Ac[(ks * 8 + mw * 4 + mt) * 128];
                af[mt][0] = ab[ilo];
                af[mt][1] = ab[32 + ilo];
                af[mt][2] = ab[64 + ihi];
                af[mt][3] = ab[96 + ihi];
            }
            unsigned bf[4][2];
#pragma unroll
            for (int nt = 0; nt < 4; nt++) {
                const unsigned* bb = &Bc[(ks * 16 + nw * 4 + nt) * 64];
                bf[nt][0] = bb[ilo];
                bf[nt][1] = bb[32 + ihi];
            }
#pragma unroll
            for (int mt = 0; mt < 4; mt++)
#pragma unroll
                for (int nt = 0; nt < 4; nt++)
                    mma_tf32(acc[mt][nt], af[mt], bf[nt][0], bf[nt][1]);
        }

        if (it + 1 < NIT) {
            proj_store(As[(it + 1) & 1], Bs[(it + 1) & 1], pa, pb,
                       ihalf, ks_w, ch_w, hi_w, gp_w);
            __syncthreads();
        }
    }

#pragma unroll
    for (int nt = 0; nt < 4; nt++) {
        const int col = n0 + nw * 32 + nt * 8 + tg * 2;
        const float2 bs = *(const float2*)&bias[col];
#pragma unroll
        for (int mt = 0; mt < 4; mt++) {
            const int r0 = m0 + mw * 64 + mt * 16 + g;
            *(float2*)&out[(size_t)r0 * EE + col] =
                make_float2(acc[mt][nt][0] + bs.x, acc[mt][nt][1] + bs.y);
            *(float2*)&out[(size_t)(r0 + 8) * EE + col] =
                make_float2(acc[mt][nt][2] + bs.x, acc[mt][nt][3] + bs.y);
        }
    }
}

// ---------------------------------------------------------------------------
extern "C" void kernel_launch(void* const* d_in, const int* in_sizes, int n_in,
                              void* d_out, int out_size) {
    const float* q = (const float*)d_in[0];
    const float* k = (const float*)d_in[1];
    const float* v = (const float*)d_in[2];
    const float* W = (const float*)d_in[3];
    const float* bias = (const float*)d_in[4];
    float* out = (float*)d_out;

    attn_mma_kernel<<<dim3(TT / 64, HH, BB), 128>>>(q, k, v, W);
    proj_kernel<<<dim3(EE / BN, (BB * TT) / BM), 256>>>(bias, out);
}

// round 8
// speedup vs baseline: 2.2468x; 2.2468x over previous
#include <cuda_runtime.h>
#include <math.h>

// Problem constants
#define BB 2
#define TT 2048
#define EE 1024
#define HH 16
#define DD 64
#define WW 64

// GEMM tiling
#define BM 128
#define BN 128
#define BK 32
#define NIT (EE / BK)

// Attention tiling: 128 queries/block, 64-key chunks, 256-key span
#define QTL 128
#define KCH 64
#define KST 68
#define VST 72
#define VS_OFF (KCH * KST)                 // 4352
#define SM_TOT (VS_OFF + KCH * VST)        // 8960 uints = 35840 B

// Scratch: attention output (tf32-rounded bits stored as float) and tf32 W
__device__ float g_y[BB * TT * EE];
__device__ unsigned g_w32[EE * EE];

__device__ __forceinline__ unsigned f2tf32(float f) {
    unsigned u;
    asm("cvt.rna.tf32.f32 %0, %1;" : "=r"(u) : "f"(f));
    return u;
}

__device__ __forceinline__ void mma_tf32(float c[4], const unsigned a[4],
                                         unsigned b0, unsigned b1) {
    asm volatile(
        "mma.sync.aligned.m16n8k8.row.col.f32.tf32.tf32.f32 "
        "{%0,%1,%2,%3}, {%4,%5,%6,%7}, {%8,%9}, {%0,%1,%2,%3};\n"
        : "+f"(c[0]), "+f"(c[1]), "+f"(c[2]), "+f"(c[3])
        : "r"(a[0]), "r"(a[1]), "r"(a[2]), "r"(a[3]), "r"(b0), "r"(b1));
}

// ---------------------------------------------------------------------------
// MMA windowed attention, 128 queries/block, P kept in registers via
// shfl-transpose (C-frag -> A-frag), per-warp key-tile skipping.
// Grid (T/128, H, B) = 512 blocks, 256 threads (8 warps x 16 q-rows).
// ---------------------------------------------------------------------------
__global__ void __launch_bounds__(256, 2)
attn_mma_kernel(const float* __restrict__ q, const float* __restrict__ k,
                const float* __restrict__ v, const float* __restrict__ W) {
    __shared__ unsigned sm[SM_TOT];

    const int tid = threadIdx.x;
    const int lane = tid & 31;
    const int w = tid >> 5;
    const int g = lane >> 2;
    const int tg = lane & 3;
    const int qb = blockIdx.x * QTL;
    const int h = blockIdx.y;
    const int b = blockIdx.z;
    const int kb = qb - WW;

    // ---- W -> tf32 conversion slice (512 blocks x 2048 floats covers W)
    {
        const int blin = (blockIdx.z * HH + blockIdx.y) * (TT / QTL) + blockIdx.x;
        const float4* src = (const float4*)&W[(size_t)blin * 2048] + tid;
        uint4* dst = (uint4*)&g_w32[(size_t)blin * 2048] + tid;
#pragma unroll
        for (int i = 0; i < 2; i++) {
            float4 x = src[i * 256];
            dst[i * 256] = make_uint4(f2tf32(x.x), f2tf32(x.y), f2tf32(x.z), f2tf32(x.w));
        }
    }

    // ---- stage Q (pre-scaled by 1/8, tf32): 128 rows, reuses K/V region
    {
        const int row = tid >> 1;
        const int s0 = (tid & 1) * 8;
        const float* src = q + ((size_t)(b * TT + qb + row) * EE + h * DD) + s0 * 4;
        unsigned* dst = &sm[row * KST + s0 * 4];
#pragma unroll
        for (int i = 0; i < 8; i++) {
            float4 x = ((const float4*)src)[i];
            ((uint4*)dst)[i] = make_uint4(f2tf32(x.x * 0.125f), f2tf32(x.y * 0.125f),
                                          f2tf32(x.z * 0.125f), f2tf32(x.w * 0.125f));
        }
    }
    __syncthreads();

    unsigned aQ[8][4];
#pragma unroll
    for (int kc = 0; kc < 8; kc++) {
        const unsigned* p0 = &sm[(w * 16 + g) * KST + kc * 8 + tg];
        aQ[kc][0] = p0[0];
        aQ[kc][1] = p0[8 * KST];
        aQ[kc][2] = p0[4];
        aQ[kc][3] = p0[8 * KST + 4];
    }
    __syncthreads();

    float oacc[8][4];
#pragma unroll
    for (int i = 0; i < 8; i++)
#pragma unroll
        for (int r = 0; r < 4; r++) oacc[i][r] = 0.f;
    float l0 = 0.f, l1 = 0.f;

    const int wlo = qb + w * 16;           // warp's first query row
    const int qr0 = wlo + g;
    const int qr1 = qr0 + 8;
    const int srcA = (lane & 28) | (tg >> 1);
    const bool odd = (tg & 1) != 0;

    for (int cc = 0; cc < 4; ++cc) {
        if (cc) __syncthreads();
        // ---- load K/V chunk (64 rows), tf32, zero-fill out-of-range rows
        {
            const int r0 = tid >> 4;
            const int sg = tid & 15;
#pragma unroll
            for (int i = 0; i < 4; i++) {
                const int row = r0 + i * 16;
                const int j = kb + cc * KCH + row;
                float4 kx = make_float4(0.f, 0.f, 0.f, 0.f);
                float4 vx = kx;
                if (j >= 0 && j < TT) {
                    const size_t base = (size_t)(b * TT + j) * EE + h * DD + sg * 4;
                    kx = *(const float4*)(k + base);
                    vx = *(const float4*)(v + base);
                }
                *(uint4*)&sm[row * KST + sg * 4] =
                    make_uint4(f2tf32(kx.x), f2tf32(kx.y), f2tf32(kx.z), f2tf32(kx.w));
                *(uint4*)&sm[VS_OFF + row * VST + sg * 4] =
                    make_uint4(f2tf32(vx.x), f2tf32(vx.y), f2tf32(vx.z), f2tf32(vx.w));
            }
        }
        __syncthreads();

        const int jc = kb + cc * KCH;
#pragma unroll
        for (int n8 = 0; n8 < 8; n8++) {
            const int jt = jc + n8 * 8;
            // warp-uniform tile skip: window + sequence bounds
            if (jt + 7 < wlo - WW || jt > wlo + 15 + WW || jt + 7 < 0 || jt >= TT)
                continue;

            // ---- S tile = Q K^T (16 q x 8 keys)
            float s[4] = {0.f, 0.f, 0.f, 0.f};
            const unsigned* kr = &sm[(n8 * 8 + g) * KST + tg];
#pragma unroll
            for (int kc = 0; kc < 8; kc++)
                mma_tf32(s, aQ[kc], kr[kc * 8], kr[kc * 8 + 4]);

            // ---- mask + exp + row-sum
            const int j0 = jt + 2 * tg;
            const int j1 = j0 + 1;
            const bool v00 = (j0 >= 0) & (j0 < TT) & (abs(qr0 - j0) <= WW);
            const bool v01 = (j1 >= 0) & (j1 < TT) & (abs(qr0 - j1) <= WW);
            const bool v10 = (j0 >= 0) & (j0 < TT) & (abs(qr1 - j0) <= WW);
            const bool v11 = (j1 >= 0) & (j1 < TT) & (abs(qr1 - j1) <= WW);
            const float p0 = v00 ? __expf(s[0]) : 0.f;
            const float p1 = v01 ? __expf(s[1]) : 0.f;
            const float p2 = v10 ? __expf(s[2]) : 0.f;
            const float p3 = v11 ? __expf(s[3]) : 0.f;
            l0 += p0 + p1;
            l1 += p2 + p3;

            // ---- shfl transpose: C-frag (p) -> A-frag (aP), tf32 bits
            const unsigned u0 = f2tf32(p0), u1 = f2tf32(p1);
            const unsigned u2 = f2tf32(p2), u3 = f2tf32(p3);
            const unsigned y0 = __shfl_sync(0xffffffffu, u0, srcA);
            const unsigned y1 = __shfl_sync(0xffffffffu, u1, srcA);
            const unsigned y2 = __shfl_sync(0xffffffffu, u0, srcA + 2);
            const unsigned y3 = __shfl_sync(0xffffffffu, u1, srcA + 2);
            const unsigned z0 = __shfl_sync(0xffffffffu, u2, srcA);
            const unsigned z1 = __shfl_sync(0xffffffffu, u3, srcA);
            const unsigned z2 = __shfl_sync(0xffffffffu, u2, srcA + 2);
            const unsigned z3 = __shfl_sync(0xffffffffu, u3, srcA + 2);
            unsigned aP[4];
            aP[0] = odd ? y1 : y0;
            aP[2] = odd ? y3 : y2;
            aP[1] = odd ? z1 : z0;
            aP[3] = odd ? z3 : z2;

            // ---- O += P V (16 q x 64 d, 8 keys)
            const unsigned* vr = &sm[VS_OFF + (n8 * 8 + tg) * VST + g];
            const unsigned* vr4 = vr + 4 * VST;
#pragma unroll
            for (int no = 0; no < 8; no++)
                mma_tf32(oacc[no], aP, vr[no * 8], vr4[no * 8]);
        }
    }

    l0 += __shfl_xor_sync(0xffffffffu, l0, 1);
    l0 += __shfl_xor_sync(0xffffffffu, l0, 2);
    l1 += __shfl_xor_sync(0xffffffffu, l1, 1);
    l1 += __shfl_xor_sync(0xffffffffu, l1, 2);
    const float i0 = 1.f / l0, i1 = 1.f / l1;

    // store tf32-rounded y so proj can consume raw bits
#pragma unroll
    for (int no = 0; no < 8; no++) {
        const int col = h * DD + no * 8 + 2 * tg;
        *(uint2*)&g_y[(size_t)(b * TT + qr0) * EE + col] =
            make_uint2(f2tf32(oacc[no][0] * i0), f2tf32(oacc[no][1] * i0));
        *(uint2*)&g_y[(size_t)(b * TT + qr1) * EE + col] =
            make_uint2(f2tf32(oacc[no][2] * i1), f2tf32(oacc[no][3] * i1));
    }
}

// ---------------------------------------------------------------------------
// tf32 tensor-core projection (round-6 version, measured 58.2us):
// 128 threads, 4 warps of 64x64, double-buffered fragment-major smem,
// register prefetch, pre-converted operands.
// ---------------------------------------------------------------------------
__device__ __forceinline__ void proj_store(unsigned* Ad, unsigned* Bd,
                                           const uint4* pa, const uint4* pb,
                                           int ks_w, int ch_w, int hi_w, int gp_w) {
    const int slotA = hi_w + 2 * ch_w;
#pragma unroll
    for (int i = 0; i < 8; i++) {
        *(uint4*)&Ad[(ks_w * 8 + i) * 128 + slotA * 32 + gp_w] = pa[i];
        *(uint4*)&Bd[(ks_w * 16 + i * 2 + hi_w) * 64 + ch_w * 32 + gp_w] = pb[i];
    }
}

__global__ void __launch_bounds__(128, 2) proj_kernel(const float* __restrict__ bias,
                                                      float* __restrict__ out) {
    __shared__ unsigned As[2][4 * 8 * 128];
    __shared__ unsigned Bs[2][4 * 16 * 64];

    const int tid = threadIdx.x;
    const int m0 = blockIdx.y * BM;
    const int n0 = blockIdx.x * BN;

    const int seg = tid & 7;
    const int rb = tid >> 3;
    const int hi_w = rb >> 3;
    const int ks_w = seg >> 1;
    const int ch_w = seg & 1;
    const int gp_w = ((rb & 7) ^ (ks_w ^ (ch_w << 2))) << 2;

    const unsigned* ysrc = (const unsigned*)g_y;
    const unsigned* asrc = &ysrc[(size_t)(m0 + rb) * EE + seg * 4];
    const unsigned* bsrc = &g_w32[(size_t)(n0 + rb) * EE + seg * 4];

    const int lane = tid & 31;
    const int wid = tid >> 5;
    const int mw = wid >> 1;
    const int nw = wid & 1;
    const int g = lane >> 2;
    const int tg = lane & 3;

    float acc[4][8][4];
#pragma unroll
    for (int i = 0; i < 4; i++)
#pragma unroll
        for (int j = 0; j < 8; j++)
#pragma unroll
            for (int r = 0; r < 4; r++) acc[i][j][r] = 0.f;

    uint4 pa[8], pb[8];
#pragma unroll
    for (int i = 0; i < 8; i++) {
        pa[i] = *(const uint4*)&asrc[(size_t)i * 16 * EE];
        pb[i] = *(const uint4*)&bsrc[(size_t)i * 16 * EE];
    }
    proj_store(As[0], Bs[0], pa, pb, ks_w, ch_w, hi_w, gp_w);
    __syncthreads();

    for (int it = 0; it < NIT; ++it) {
        const unsigned* Ac = As[it & 1];
        const unsigned* Bc = Bs[it & 1];

        if (it + 1 < NIT) {
            const int kk = (it + 1) * BK;
#pragma unroll
            for (int i = 0; i < 8; i++) {
                pa[i] = *(const uint4*)&asrc[(size_t)i * 16 * EE + kk];
                pb[i] = *(const uint4*)&bsrc[(size_t)i * 16 * EE + kk];
            }
        }

#pragma unroll
        for (int ks = 0; ks < 4; ++ks) {
            const int ilo = ((g ^ ks) << 2) + tg;
            const int ihi = ((g ^ ks ^ 4) << 2) + tg;
            unsigned af[4][4];
#pragma unroll
            for (int mt = 0; mt < 4; mt++) {
                const unsigned* ab = &Ac[(ks * 8 + mw * 4 + mt) * 128];
                af[mt][0] = ab[ilo];
                af[mt][1] = ab[32 + ilo];
                af[mt][2] = ab[64 + ihi];
                af[mt][3] = ab[96 + ihi];
            }
            unsigned bf[8][2];
#pragma unroll
            for (int nt = 0; nt < 8; nt++) {
                const unsigned* bb = &Bc[(ks * 16 + nw * 8 + nt) * 64];
                bf[nt][0] = bb[ilo];
                bf[nt][1] = bb[32 + ihi];
            }
#pragma unroll
            for (int mt = 0; mt < 4; mt++)
#pragma unroll
                for (int nt = 0; nt < 8; nt++)
                    mma_tf32(acc[mt][nt], af[mt], bf[nt][0], bf[nt][1]);
        }

        if (it + 1 < NIT) {
            proj_store(As[(it + 1) & 1], Bs[(it + 1) & 1], pa, pb,
                       ks_w, ch_w, hi_w, gp_w);
            __syncthreads();
        }
    }

#pragma unroll
    for (int nt = 0; nt < 8; nt++) {
        const int col = n0 + nw * 64 + nt * 8 + tg * 2;
        const float2 bs = *(const float2*)&bias[col];
#pragma unroll
        for (int mt = 0; mt < 4; mt++) {
            const int r0 = m0 + mw * 64 + mt * 16 + g;
            *(float2*)&out[(size_t)r0 * EE + col] =
                make_float2(acc[mt][nt][0] + bs.x, acc[mt][nt][1] + bs.y);
            *(float2*)&out[(size_t)(r0 + 8) * EE + col] =
                make_float2(acc[mt][nt][2] + bs.x, acc[mt][nt][3] + bs.y);
        }
    }
}

// ---------------------------------------------------------------------------
extern "C" void kernel_launch(void* const* d_in, const int* in_sizes, int n_in,
                              void* d_out, int out_size) {
    const float* q = (const float*)d_in[0];
    const float* k = (const float*)d_in[1];
    const float* v = (const float*)d_in[2];
    const float* W = (const float*)d_in[3];
    const float* bias = (const float*)d_in[4];
    float* out = (float*)d_out;

    attn_mma_kernel<<<dim3(TT / QTL, HH, BB), 256>>>(q, k, v, W);
    proj_kernel<<<dim3(EE / BN, (BB * TT) / BM), 128>>>(bias, out);
}